// round 1
// baseline (speedup 1.0000x reference)
#include <cuda_runtime.h>
#include <cstdint>

// Shapes (hardcoded from reference setup_inputs)
#define Td 4
#define Bd 32
#define Cd 384
#define HWd 256
#define NTOT 32768          // Td*Bd*HWd
#define TBN 8192            // Bd*HWd (stride per t inside j)
#define HEADS 8
#define CHD 48
#define EPSB 1e-5f
#define NELEM 12582912      // Td*Bd*Cd*HWd

// Scratch (statics are the sanctioned no-alloc workaround)
__device__ float g_xs[Cd * NTOT];    // shortcut-LIF spikes, layout [c][(t*B+b)*HW+n]
__device__ float g_tmp[Cd * NTOT];   // conv output / y buffer
__device__ float g_qs[Cd * NTOT];
__device__ float g_ks[Cd * NTOT];
__device__ float g_vs[Cd * NTOT];
__device__ float g_kvs[Td * Bd * Cd];
__device__ float g_scale[4 * Cd];
__device__ float g_bias[4 * Cd];

// ---------------------------------------------------------------------------
// Fold BN (and proj bias) into per-row affine: val = conv*scale + bias
// ---------------------------------------------------------------------------
__global__ void prep_kernel(
    const float* qg, const float* qb, const float* qm, const float* qv,
    const float* kg, const float* kb, const float* km, const float* kvv,
    const float* vg, const float* vb, const float* vm, const float* vvv,
    const float* pb, const float* pg, const float* pbe, const float* pm, const float* pv)
{
    int d = threadIdx.x;
    if (d >= Cd) return;
    float s;
    s = qg[d] * rsqrtf(qv[d] + EPSB);  g_scale[d]        = s; g_bias[d]        = qb[d] - qm[d] * s;
    s = kg[d] * rsqrtf(kvv[d] + EPSB); g_scale[Cd + d]   = s; g_bias[Cd + d]   = kb[d] - km[d] * s;
    s = vg[d] * rsqrtf(vvv[d] + EPSB); g_scale[2*Cd + d] = s; g_bias[2*Cd + d] = vb[d] - vm[d] * s;
    s = pg[d] * rsqrtf(pv[d] + EPSB);  g_scale[3*Cd + d] = s; g_bias[3*Cd + d] = (pb[d] - pm[d]) * s + pbe[d];
}

// ---------------------------------------------------------------------------
// xs = lif(x): v' = 0.5*(v+x); s = (v'>=1); v = v'*(1-s)
// read x in (t,b,c,n); write spikes in [c][(t*B+b)*HW+n]
// ---------------------------------------------------------------------------
__global__ void lif_x_kernel(const float* __restrict__ x)
{
    int tid = blockIdx.x * 256 + threadIdx.x;    // over Bd*Cd*HWd
    if (tid >= Bd * Cd * HWd) return;
    int n = tid % HWd;
    int c = (tid / HWd) % Cd;
    int b = tid / (HWd * Cd);
    float v = 0.f;
#pragma unroll
    for (int t = 0; t < Td; t++) {
        float xv = x[(size_t)((t * Bd + b) * Cd + c) * HWd + n];
        v = 0.5f * (v + xv);
        float s = (v >= 1.0f) ? 1.f : 0.f;
        v *= (1.f - s);
        g_xs[(size_t)c * NTOT + (size_t)(t * Bd + b) * HWd + n] = s;
    }
}

// ---------------------------------------------------------------------------
// SGEMM: out[row, j] = sum_c A[row,c] * Bm[c, j],  M=K=384, N=NTOT
// Epilogue MODE 0: out = z*scale[row]+bias[row] (contiguous [row][j])
// Epilogue MODE 1: scatter to (t,b,c,n) layout, add identity (proj + residual)
// ---------------------------------------------------------------------------
template <int MODE>
__global__ void __launch_bounds__(256) sgemm_kernel(
    const float* __restrict__ A, const float* __restrict__ Bm,
    float* __restrict__ out, const float* __restrict__ scale,
    const float* __restrict__ bias, const float* __restrict__ identity)
{
    __shared__ float As[16][128];
    __shared__ float Bs[16][64];
    const int tid = threadIdx.x;
    const int tx = tid & 15, ty = tid >> 4;
    const int m0 = blockIdx.y * 128;
    const int n0 = blockIdx.x * 64;
    float acc[8][4] = {};

    for (int k0 = 0; k0 < Cd; k0 += 16) {
#pragma unroll
        for (int it = 0; it < 2; it++) {
            int i4 = tid + it * 256;
            int row = i4 >> 2, c4 = (i4 & 3) * 4;
            float4 av = *reinterpret_cast<const float4*>(&A[(size_t)(m0 + row) * Cd + k0 + c4]);
            As[c4 + 0][row] = av.x; As[c4 + 1][row] = av.y;
            As[c4 + 2][row] = av.z; As[c4 + 3][row] = av.w;
        }
        {
            int row = tid >> 4, c4 = (tid & 15) * 4;
            *reinterpret_cast<float4*>(&Bs[row][c4]) =
                *reinterpret_cast<const float4*>(&Bm[(size_t)(k0 + row) * NTOT + n0 + c4]);
        }
        __syncthreads();
#pragma unroll
        for (int kk = 0; kk < 16; kk++) {
            float4 a0 = *reinterpret_cast<float4*>(&As[kk][ty * 8]);
            float4 a1 = *reinterpret_cast<float4*>(&As[kk][ty * 8 + 4]);
            float4 b0 = *reinterpret_cast<float4*>(&Bs[kk][tx * 4]);
            float a[8] = {a0.x, a0.y, a0.z, a0.w, a1.x, a1.y, a1.z, a1.w};
            float b[4] = {b0.x, b0.y, b0.z, b0.w};
#pragma unroll
            for (int i = 0; i < 8; i++)
#pragma unroll
                for (int j = 0; j < 4; j++)
                    acc[i][j] += a[i] * b[j];
        }
        __syncthreads();
    }

#pragma unroll
    for (int i = 0; i < 8; i++) {
        int row = m0 + ty * 8 + i;
        float sc = scale[row], bi = bias[row];
#pragma unroll
        for (int j = 0; j < 4; j++) {
            int col = n0 + tx * 4 + j;
            float val = acc[i][j] * sc + bi;
            if (MODE == 0) {
                out[(size_t)row * NTOT + col] = val;
            } else {
                int tb = col >> 8, n = col & 255;
                size_t oi = ((size_t)tb * Cd + row) * HWd + n;
                out[oi] = val + identity[oi];
            }
        }
    }
}

// ---------------------------------------------------------------------------
// Temporal LIF over the BN'ed conv output (v_th = 1), layout [c][(t,b,n)]
// ---------------------------------------------------------------------------
__global__ void lif_t_kernel(const float* __restrict__ z, float* __restrict__ sout)
{
    int tid = blockIdx.x * 256 + threadIdx.x;   // over Cd*TBN
    if (tid >= Cd * TBN) return;
    int d = tid / TBN, bn = tid - d * TBN;
    size_t base = (size_t)d * NTOT + bn;
    float v = 0.f;
#pragma unroll
    for (int t = 0; t < Td; t++) {
        float xv = z[base + (size_t)t * TBN];
        v = 0.5f * (v + xv);
        float s = (v >= 1.0f) ? 1.f : 0.f;
        v *= (1.f - s);
        sout[base + (size_t)t * TBN] = s;
    }
}

// ---------------------------------------------------------------------------
// kv = lif( sum_n k*v , v_th=0.5 ).  One block per (b,c); 256 threads over n.
// ---------------------------------------------------------------------------
__global__ void kv_kernel()
{
    int bc = blockIdx.x;          // Bd*Cd blocks
    int c = bc % Cd, b = bc / Cd;
    int n = threadIdx.x;
    float p[Td];
#pragma unroll
    for (int t = 0; t < Td; t++) {
        size_t idx = (size_t)c * NTOT + (size_t)(t * Bd + b) * HWd + n;
        p[t] = g_ks[idx] * g_vs[idx];
    }
#pragma unroll
    for (int t = 0; t < Td; t++)
        for (int o = 16; o > 0; o >>= 1) p[t] += __shfl_down_sync(0xffffffffu, p[t], o);
    __shared__ float wsum[Td][8];
    int lane = n & 31, wid = n >> 5;
    if (lane == 0)
#pragma unroll
        for (int t = 0; t < Td; t++) wsum[t][wid] = p[t];
    __syncthreads();
    if (n == 0) {
        float v = 0.f;
#pragma unroll
        for (int t = 0; t < Td; t++) {
            float kvp = 0.f;
#pragma unroll
            for (int w = 0; w < 8; w++) kvp += wsum[t][w];
            v = 0.5f * (v + kvp);
            float s = (v >= 0.5f) ? 1.f : 0.f;
            v *= (1.f - s);
            g_kvs[(size_t)(t * Bd + b) * Cd + c] = s;
        }
    }
}

// ---------------------------------------------------------------------------
// y = q * kv  (broadcast kv over spatial n) -> g_tmp, same [c][(t,b,n)] layout
// ---------------------------------------------------------------------------
__global__ void y_kernel()
{
    int tid = blockIdx.x * 256 + threadIdx.x;  // over Cd*NTOT, exact grid
    int c = tid / NTOT;
    int j = tid - c * NTOT;
    int tb = j >> 8;
    g_tmp[tid] = g_qs[tid] * g_kvs[(size_t)tb * Cd + c];
}

// ---------------------------------------------------------------------------
// Second output: v spikes in (T,B,heads,N,Ch) layout
// ---------------------------------------------------------------------------
__global__ void vout_kernel(float* __restrict__ out2)
{
    int tid = blockIdx.x * 256 + threadIdx.x;  // over NELEM, exact grid
    int ch = tid % CHD;
    int rest = tid / CHD;
    int n = rest % HWd;
    rest /= HWd;
    int head = rest % HEADS;
    int tb = rest / HEADS;
    int c = head * CHD + ch;
    out2[tid] = g_vs[(size_t)c * NTOT + (size_t)tb * HWd + n];
}

// ---------------------------------------------------------------------------
extern "C" void kernel_launch(void* const* d_in, const int* in_sizes, int n_in,
                              void* d_out, int out_size)
{
    const float* x   = (const float*)d_in[0];
    const float* qw  = (const float*)d_in[1];
    const float* qg  = (const float*)d_in[2];
    const float* qb  = (const float*)d_in[3];
    const float* qm  = (const float*)d_in[4];
    const float* qv  = (const float*)d_in[5];
    const float* kw  = (const float*)d_in[6];
    const float* kg  = (const float*)d_in[7];
    const float* kb  = (const float*)d_in[8];
    const float* km  = (const float*)d_in[9];
    const float* kv  = (const float*)d_in[10];
    const float* vw  = (const float*)d_in[11];
    const float* vg  = (const float*)d_in[12];
    const float* vb  = (const float*)d_in[13];
    const float* vm  = (const float*)d_in[14];
    const float* vv  = (const float*)d_in[15];
    const float* pw  = (const float*)d_in[16];
    const float* pb  = (const float*)d_in[17];
    const float* pg  = (const float*)d_in[18];
    const float* pbe = (const float*)d_in[19];
    const float* pm  = (const float*)d_in[20];
    const float* pv  = (const float*)d_in[21];

    float *p_xs, *p_tmp, *p_qs, *p_ks, *p_vs, *p_scale, *p_bias;
    cudaGetSymbolAddress((void**)&p_xs, g_xs);
    cudaGetSymbolAddress((void**)&p_tmp, g_tmp);
    cudaGetSymbolAddress((void**)&p_qs, g_qs);
    cudaGetSymbolAddress((void**)&p_ks, g_ks);
    cudaGetSymbolAddress((void**)&p_vs, g_vs);
    cudaGetSymbolAddress((void**)&p_scale, g_scale);
    cudaGetSymbolAddress((void**)&p_bias, g_bias);

    float* out = (float*)d_out;

    prep_kernel<<<1, 384>>>(qg, qb, qm, qv, kg, kb, km, kv, vg, vb, vm, vv,
                            pb, pg, pbe, pm, pv);
    lif_x_kernel<<<12288, 256>>>(x);

    dim3 gg(NTOT / 64, Cd / 128);
    sgemm_kernel<0><<<gg, 256>>>(qw, p_xs, p_tmp, p_scale,          p_bias,          nullptr);
    lif_t_kernel<<<12288, 256>>>(p_tmp, p_qs);
    sgemm_kernel<0><<<gg, 256>>>(kw, p_xs, p_tmp, p_scale + Cd,     p_bias + Cd,     nullptr);
    lif_t_kernel<<<12288, 256>>>(p_tmp, p_ks);
    sgemm_kernel<0><<<gg, 256>>>(vw, p_xs, p_tmp, p_scale + 2 * Cd, p_bias + 2 * Cd, nullptr);
    lif_t_kernel<<<12288, 256>>>(p_tmp, p_vs);

    kv_kernel<<<Bd * Cd, 256>>>();
    y_kernel<<<NELEM / 256, 256>>>();

    sgemm_kernel<1><<<gg, 256>>>(pw, p_tmp, out, p_scale + 3 * Cd, p_bias + 3 * Cd, x);

    if (out_size >= 2 * NELEM)
        vout_kernel<<<NELEM / 256, 256>>>(out + NELEM);
}

// round 2
// speedup vs baseline: 1.8714x; 1.8714x over previous
#include <cuda_runtime.h>
#include <cuda_bf16.h>
#include <cstdint>

#define Td 4
#define Bd 32
#define Cd 384
#define HWd 256
#define NTOT 32768          // Td*Bd*HWd
#define TBN 8192            // Bd*HWd
#define HEADS 8
#define CHD 48
#define EPSB 1e-5f
#define NELEM 12582912      // Td*Bd*Cd*HWd

// ---- scratch (device statics = sanctioned no-alloc workaround) ----
__device__ __nv_bfloat16 g_sx[Cd * NTOT];            // shortcut-LIF spikes [c][(t*B+b)*HW+n]
__device__ float         g_z[3 * Cd * NTOT];         // qkv conv outputs (BN'ed), rows 0..1151
__device__ __nv_bfloat16 g_sqkv[3 * Cd * NTOT];      // q,k,v spikes (rows 0..1151)
__device__ __nv_bfloat16 g_y[Cd * NTOT];             // y = q * kv (binary)
__device__ __nv_bfloat16 g_kvs[Td * Bd * Cd];        // talking-heads spikes
__device__ __nv_bfloat16 g_w[3][4 * Cd][Cd];         // 3-term split weights [term][q|k|v|proj row][cin]
__device__ float g_scale[4 * Cd];
__device__ float g_bias[4 * Cd];

// ---------------------------------------------------------------------------
// PTX helpers
// ---------------------------------------------------------------------------
__device__ __forceinline__ uint32_t cvta_smem(const void* p) {
    uint32_t a;
    asm("{ .reg .u64 t; cvta.to.shared.u64 t, %1; cvt.u32.u64 %0, t; }" : "=r"(a) : "l"(p));
    return a;
}
__device__ __forceinline__ void ldsm_x4(uint32_t& r0, uint32_t& r1, uint32_t& r2, uint32_t& r3, uint32_t a) {
    asm volatile("ldmatrix.sync.aligned.m8n8.x4.shared.b16 {%0,%1,%2,%3},[%4];"
                 : "=r"(r0), "=r"(r1), "=r"(r2), "=r"(r3) : "r"(a));
}
__device__ __forceinline__ void ldsm_x4t(uint32_t& r0, uint32_t& r1, uint32_t& r2, uint32_t& r3, uint32_t a) {
    asm volatile("ldmatrix.sync.aligned.m8n8.x4.trans.shared.b16 {%0,%1,%2,%3},[%4];"
                 : "=r"(r0), "=r"(r1), "=r"(r2), "=r"(r3) : "r"(a));
}
__device__ __forceinline__ void mma_bf16(float* d, const uint32_t* a, const uint32_t* b) {
    asm volatile("mma.sync.aligned.m16n8k16.row.col.f32.bf16.bf16.f32 "
                 "{%0,%1,%2,%3},{%4,%5,%6,%7},{%8,%9},{%0,%1,%2,%3};"
                 : "+f"(d[0]), "+f"(d[1]), "+f"(d[2]), "+f"(d[3])
                 : "r"(a[0]), "r"(a[1]), "r"(a[2]), "r"(a[3]), "r"(b[0]), "r"(b[1]));
}

// ---------------------------------------------------------------------------
// BN fold: per-row affine (rows stacked q,k,v,proj -> matches GEMM row index)
// ---------------------------------------------------------------------------
__global__ void prep_kernel(
    const float* qg, const float* qb, const float* qm, const float* qv,
    const float* kg, const float* kb, const float* km, const float* kvv,
    const float* vg, const float* vb, const float* vm, const float* vvv,
    const float* pb, const float* pg, const float* pbe, const float* pm, const float* pv)
{
    int d = threadIdx.x;
    if (d >= Cd) return;
    float s;
    s = qg[d] * rsqrtf(qv[d] + EPSB);  g_scale[d]          = s; g_bias[d]          = qb[d] - qm[d] * s;
    s = kg[d] * rsqrtf(kvv[d] + EPSB); g_scale[Cd + d]     = s; g_bias[Cd + d]     = kb[d] - km[d] * s;
    s = vg[d] * rsqrtf(vvv[d] + EPSB); g_scale[2*Cd + d]   = s; g_bias[2*Cd + d]   = vb[d] - vm[d] * s;
    s = pg[d] * rsqrtf(pv[d] + EPSB);  g_scale[3*Cd + d]   = s; g_bias[3*Cd + d]   = (pb[d] - pm[d]) * s + pbe[d];
}

// 3-term bf16 split of all four weight matrices (exact to 2^-24 relative)
__global__ void wsplit_kernel(const float* __restrict__ qw, const float* __restrict__ kw,
                              const float* __restrict__ vw, const float* __restrict__ pw)
{
    int tid = blockIdx.x * 256 + threadIdx.x;      // 1536*384 exact
    int row = tid / Cd, cin = tid - row * Cd;
    const float* src = (row < Cd) ? qw : (row < 2*Cd) ? kw : (row < 3*Cd) ? vw : pw;
    float w = src[(row % Cd) * Cd + cin];
    __nv_bfloat16 hi = __float2bfloat16(w);
    float r1 = w - __bfloat162float(hi);
    __nv_bfloat16 mid = __float2bfloat16(r1);
    float r2 = r1 - __bfloat162float(mid);
    g_w[0][row][cin] = hi;
    g_w[1][row][cin] = mid;
    g_w[2][row][cin] = __float2bfloat16(r2);
}

// ---------------------------------------------------------------------------
// xs = lif(x), write bf16 spikes in [c][(t*B+b)*HW+n]
// ---------------------------------------------------------------------------
__global__ void lif_x_kernel(const float* __restrict__ x)
{
    int tid = blockIdx.x * 256 + threadIdx.x;      // Bd*Cd*HWd exact
    int n = tid % HWd;
    int c = (tid / HWd) % Cd;
    int b = tid / (HWd * Cd);
    float v = 0.f;
#pragma unroll
    for (int t = 0; t < Td; t++) {
        float xv = x[(size_t)((t * Bd + b) * Cd + c) * HWd + n];
        v = 0.5f * (v + xv);
        float s = (v >= 1.0f) ? 1.f : 0.f;
        v *= (1.f - s);
        g_sx[(size_t)c * NTOT + (size_t)(t * Bd + b) * HWd + n] = __float2bfloat16(s);
    }
}

// ---------------------------------------------------------------------------
// Tensor-core GEMM: out[row, j] = sum_c (sum_terms w_t[row,c]) * B[c, j]
// A = g_w[term][row_off + m][c] (bf16, 3 terms), B = spikes bf16 [Cd][NTOT].
// MODE 0: out fp32 [row][NTOT] = acc*scale+bias
// MODE 1: scatter to (t,b,c,n), add identity (proj + residual)
// Block tile 128x128xBK32, warps 2(M)x4(N), warp tile 64x32.
// ---------------------------------------------------------------------------
template <int MODE>
__global__ void __launch_bounds__(256, 2) mma_gemm(
    const __nv_bfloat16* __restrict__ Bmat, float* __restrict__ out,
    int row_off, const float* __restrict__ identity)
{
    __shared__ alignas(16) __nv_bfloat16 As[3][128][40];   // +8 pad
    __shared__ alignas(16) __nv_bfloat16 Bs[32][136];      // +8 pad

    const int tid = threadIdx.x;
    const int warp = tid >> 5, lane = tid & 31;
    const int wm0 = (warp >> 2) * 64, wn0 = (warp & 3) * 32;
    const int m_blk = blockIdx.y * 128;
    const int n_blk = blockIdx.x * 128;

    float acc[4][4][4];
#pragma unroll
    for (int i = 0; i < 4; i++)
#pragma unroll
        for (int j = 0; j < 4; j++)
#pragma unroll
            for (int r = 0; r < 4; r++) acc[i][j][r] = 0.f;

    for (int k0 = 0; k0 < Cd; k0 += 32) {
#pragma unroll
        for (int term = 0; term < 3; term++) {
#pragma unroll
            for (int it = 0; it < 2; it++) {
                int idx = (tid + it * 256) * 8;          // elem in 128x32
                int r = idx >> 5, c = idx & 31;
                float4 v4 = *(const float4*)&g_w[term][row_off + m_blk + r][k0 + c];
                *(float4*)&As[term][r][c] = v4;
            }
        }
#pragma unroll
        for (int it = 0; it < 2; it++) {
            int idx = (tid + it * 256) * 8;              // elem in 32x128
            int r = idx >> 7, c = idx & 127;
            float4 v4 = *(const float4*)&Bmat[(size_t)(k0 + r) * NTOT + n_blk + c];
            *(float4*)&Bs[r][c] = v4;
        }
        __syncthreads();

#pragma unroll
        for (int ks = 0; ks < 2; ks++) {
            const int kk = ks * 16;
            uint32_t bfrag[4][2];
#pragma unroll
            for (int h = 0; h < 2; h++) {
                uint32_t r0, r1, r2, r3;
                uint32_t a = cvta_smem(&Bs[kk + (lane & 15)][wn0 + h * 16 + (lane >> 4) * 8]);
                ldsm_x4t(r0, r1, r2, r3, a);
                bfrag[h * 2][0] = r0;     bfrag[h * 2][1] = r1;
                bfrag[h * 2 + 1][0] = r2; bfrag[h * 2 + 1][1] = r3;
            }
#pragma unroll
            for (int term = 0; term < 3; term++) {
#pragma unroll
                for (int mt = 0; mt < 4; mt++) {
                    uint32_t afrag[4];
                    uint32_t a = cvta_smem(&As[term][wm0 + mt * 16 + (lane & 15)][kk + (lane >> 4) * 8]);
                    ldsm_x4(afrag[0], afrag[1], afrag[2], afrag[3], a);
#pragma unroll
                    for (int nt = 0; nt < 4; nt++)
                        mma_bf16(acc[mt][nt], afrag, bfrag[nt]);
                }
            }
        }
        __syncthreads();
    }

    const int g = lane >> 2, tig = lane & 3;
#pragma unroll
    for (int mt = 0; mt < 4; mt++) {
#pragma unroll
        for (int i = 0; i < 2; i++) {
            int row = m_blk + wm0 + mt * 16 + g + i * 8;
            float sc = g_scale[row_off + row], bi = g_bias[row_off + row];
#pragma unroll
            for (int nt = 0; nt < 4; nt++) {
#pragma unroll
                for (int j = 0; j < 2; j++) {
                    int col = n_blk + wn0 + nt * 8 + tig * 2 + j;
                    float val = acc[mt][nt][i * 2 + j] * sc + bi;
                    if (MODE == 0) {
                        out[(size_t)row * NTOT + col] = val;
                    } else {
                        int tb = col >> 8, n = col & 255;
                        size_t oi = ((size_t)tb * Cd + row) * HWd + n;
                        out[oi] = val + identity[oi];
                    }
                }
            }
        }
    }
}

// ---------------------------------------------------------------------------
// Temporal LIF over g_z rows 0..1151 -> bf16 spikes g_sqkv
// ---------------------------------------------------------------------------
__global__ void lif_t_kernel()
{
    int tid = blockIdx.x * 256 + threadIdx.x;    // 1152*TBN exact
    int row = tid / TBN, bn = tid - row * TBN;
    size_t base = (size_t)row * NTOT + bn;
    float v = 0.f;
#pragma unroll
    for (int t = 0; t < Td; t++) {
        float xv = g_z[base + (size_t)t * TBN];
        v = 0.5f * (v + xv);
        float s = (v >= 1.0f) ? 1.f : 0.f;
        v *= (1.f - s);
        g_sqkv[base + (size_t)t * TBN] = __float2bfloat16(s);
    }
}

// ---------------------------------------------------------------------------
// kv = lif( sum_n k*v , v_th=0.5 ): block per (b,c)
// ---------------------------------------------------------------------------
__global__ void kv_kernel()
{
    int bc = blockIdx.x;
    int c = bc % Cd, b = bc / Cd;
    int n = threadIdx.x;
    float p[Td];
#pragma unroll
    for (int t = 0; t < Td; t++) {
        size_t o = (size_t)(t * Bd + b) * HWd + n;
        float kk = __bfloat162float(g_sqkv[(size_t)(Cd + c) * NTOT + o]);
        float vv = __bfloat162float(g_sqkv[(size_t)(2 * Cd + c) * NTOT + o]);
        p[t] = kk * vv;
    }
#pragma unroll
    for (int t = 0; t < Td; t++)
        for (int o = 16; o > 0; o >>= 1) p[t] += __shfl_down_sync(0xffffffffu, p[t], o);
    __shared__ float wsum[Td][8];
    int lane = n & 31, wid = n >> 5;
    if (lane == 0)
#pragma unroll
        for (int t = 0; t < Td; t++) wsum[t][wid] = p[t];
    __syncthreads();
    if (n == 0) {
        float v = 0.f;
#pragma unroll
        for (int t = 0; t < Td; t++) {
            float kvp = 0.f;
#pragma unroll
            for (int w = 0; w < 8; w++) kvp += wsum[t][w];
            v = 0.5f * (v + kvp);
            float s = (v >= 0.5f) ? 1.f : 0.f;
            v *= (1.f - s);
            g_kvs[(size_t)(t * Bd + b) * Cd + c] = __float2bfloat16(s);
        }
    }
}

// ---------------------------------------------------------------------------
// y = q * kv (binary product, exact in bf16)
// ---------------------------------------------------------------------------
__global__ void y_kernel()
{
    int tid = blockIdx.x * 256 + threadIdx.x;    // Cd*NTOT exact
    int c = tid / NTOT;
    int j = tid - c * NTOT;
    int tb = j >> 8;
    float q = __bfloat162float(g_sqkv[tid]);     // q rows are first
    float kv = __bfloat162float(g_kvs[(size_t)tb * Cd + c]);
    g_y[tid] = __float2bfloat16(q * kv);
}

// ---------------------------------------------------------------------------
// Second output: v spikes in (T,B,heads,N,Ch) layout (fp32)
// ---------------------------------------------------------------------------
__global__ void vout_kernel(float* __restrict__ out2)
{
    int tid = blockIdx.x * 256 + threadIdx.x;    // NELEM exact
    int ch = tid % CHD;
    int rest = tid / CHD;
    int n = rest % HWd;
    rest /= HWd;
    int head = rest % HEADS;
    int tb = rest / HEADS;
    int c = head * CHD + ch;
    out2[tid] = __bfloat162float(g_sqkv[(size_t)(2 * Cd + c) * NTOT + (size_t)tb * HWd + n]);
}

// ---------------------------------------------------------------------------
extern "C" void kernel_launch(void* const* d_in, const int* in_sizes, int n_in,
                              void* d_out, int out_size)
{
    const float* x   = (const float*)d_in[0];
    const float* qw  = (const float*)d_in[1];
    const float* qg  = (const float*)d_in[2];
    const float* qb  = (const float*)d_in[3];
    const float* qm  = (const float*)d_in[4];
    const float* qv  = (const float*)d_in[5];
    const float* kw  = (const float*)d_in[6];
    const float* kg  = (const float*)d_in[7];
    const float* kb  = (const float*)d_in[8];
    const float* km  = (const float*)d_in[9];
    const float* kv  = (const float*)d_in[10];
    const float* vw  = (const float*)d_in[11];
    const float* vg  = (const float*)d_in[12];
    const float* vb  = (const float*)d_in[13];
    const float* vm  = (const float*)d_in[14];
    const float* vv  = (const float*)d_in[15];
    const float* pw  = (const float*)d_in[16];
    const float* pb  = (const float*)d_in[17];
    const float* pg  = (const float*)d_in[18];
    const float* pbe = (const float*)d_in[19];
    const float* pm  = (const float*)d_in[20];
    const float* pv  = (const float*)d_in[21];

    __nv_bfloat16 *p_sx, *p_sy;
    float *p_z;
    cudaGetSymbolAddress((void**)&p_sx, g_sx);
    cudaGetSymbolAddress((void**)&p_sy, g_y);
    cudaGetSymbolAddress((void**)&p_z, g_z);

    float* out = (float*)d_out;

    prep_kernel<<<1, 384>>>(qg, qb, qm, qv, kg, kb, km, kv, vg, vb, vm, vv,
                            pb, pg, pbe, pm, pv);
    wsplit_kernel<<<2304, 256>>>(qw, kw, vw, pw);
    lif_x_kernel<<<12288, 256>>>(x);

    dim3 g1(NTOT / 128, 9);                       // M=1152 stacked q,k,v
    mma_gemm<0><<<g1, 256>>>(p_sx, p_z, 0, nullptr);
    lif_t_kernel<<<36864, 256>>>();

    kv_kernel<<<Bd * Cd, 256>>>();
    y_kernel<<<Cd * NTOT / 256, 256>>>();

    dim3 g2(NTOT / 128, 3);                       // proj: M=384
    mma_gemm<1><<<g2, 256>>>(p_sy, out, 3 * Cd, x);

    if (out_size >= 2 * NELEM)
        vout_kernel<<<NELEM / 256, 256>>>(out + NELEM);
}